// round 10
// baseline (speedup 1.0000x reference)
#include <cuda_runtime.h>

// AlarmworkRNN collapsed to a vector RNN (only sequence row 2047 matters).
// Round 10: R9 scaffold with the single counter split into 8 per-line group
// counters (16 CTAs per counter) — removes ~1000 cyc/step of same-address
// RMW serialization at the LTS. Arrive/poll use the R7-proven
// red.release / ld.acquire pair.

#define GRID  128
#define BLOCK 512
#define NSTEP 256
#define NGRP  8            // counter groups
#define GSIZE (GRID / NGRP)

__device__ unsigned g_cnt[NGRP * 32];     // one counter per 128B line
__device__ float2 g_z[2][1024];           // parity-buffered {z1, z2}
__device__ float g_U[2][NSTEP][1024];     // u1/u2 per step (bias folded)

__global__ void rnn_init_kernel() {
    int tid = threadIdx.x;
    if (tid < NGRP * 32) g_cnt[tid] = 0u;
    g_z[0][tid] = make_float2(0.0f, 0.0f);    // blockDim = 1024
}

__device__ __forceinline__ void arrive_release(unsigned* p) {
    asm volatile("red.release.gpu.global.add.u32 [%0], %1;"
                 :: "l"(p), "r"(1u) : "memory");
}
__device__ __forceinline__ unsigned ld_acquire_gpu(unsigned* p) {
    unsigned v;
    asm volatile("ld.acquire.gpu.global.u32 %0, [%1];"
                 : "=r"(v) : "l"(p) : "memory");
    return v;
}
__device__ __forceinline__ float4 ldcg4(const float4* p) {
    float4 u;
    asm volatile("ld.global.cg.v4.f32 {%0,%1,%2,%3}, [%4];"
                 : "=f"(u.x), "=f"(u.y), "=f"(u.z), "=f"(u.w)
                 : "l"(p) : "memory");
    return u;
}

// Group-counter barrier: arrive on own group's line, poll all NGRP lines.
__device__ __forceinline__ void gbar(int tid, int warp, int lane,
                                     unsigned grp, unsigned step1) {
    if (tid == 0)
        arrive_release(&g_cnt[grp * 32]);
    if (warp == 0) {
        const unsigned target = step1 * (unsigned)GSIZE;
        const bool passive = (lane >= NGRP);
        for (;;) {
            bool ok = passive || (ld_acquire_gpu(&g_cnt[lane * 32]) >= target);
            if (__all_sync(0xffffffffu, ok)) break;
        }
    }
    __syncthreads();
}

// ---- k1: U[m][t][j] = x[t,2047,:] @ W_in_m[:,j] + b_m[j] ----
__global__ __launch_bounds__(256)
void u_kernel(const float* __restrict__ x,
              const float* __restrict__ W_in1, const float* __restrict__ b_in1,
              const float* __restrict__ W_in2, const float* __restrict__ b_in2)
{
    __shared__ float xs[8][256];
    const int b   = blockIdx.x;
    const int m   = b >> 7;
    const int jt  = (b >> 5) & 3;
    const int t0  = (b & 31) * 8;
    const int tid = threadIdx.x;
    const float* W  = m ? W_in2 : W_in1;
    const float* bi = m ? b_in2 : b_in1;

    for (int i = tid; i < 8 * 256; i += 256) {
        int tr = i >> 8, k = i & 255;
        xs[tr][k] = x[((size_t)(t0 + tr) * 2048 + 2047) * 256 + k];
    }
    __syncthreads();

    const int j = jt * 256 + tid;
    float acc[8];
    const float bj = bi[j];
    #pragma unroll
    for (int r = 0; r < 8; r++) acc[r] = bj;
    #pragma unroll 8
    for (int k = 0; k < 256; k++) {
        float w = W[k * 1024 + j];
        #pragma unroll
        for (int r = 0; r < 8; r++) acc[r] += xs[r][k] * w;
    }
    #pragma unroll
    for (int r = 0; r < 8; r++) g_U[m][t0 + r][j] = acc[r];
}

// ---- k2: persistent recurrence + in-loop out ----
__global__ __launch_bounds__(BLOCK, 1)
void rnn_main_kernel(const float* __restrict__ W_rec1,
                     const float* __restrict__ W_rec2,
                     const float* __restrict__ W_out,
                     const float* __restrict__ b_out,
                     float* __restrict__ out)
{
    extern __shared__ float sm[];
    float* e1     = sm;                 // [1024]  z1 + z2
    float* e2     = e1 + 1024;          // [1024]  z2
    float* z1s    = e2 + 1024;          // [2][1024] z1 snapshots by parity
    float* wout_s = z1s + 2048;         // [2][1024] this CTA's W_out columns
    float* stage  = wout_s + 2048;      // [1024*9] weight staging (preload only)

    const int tid  = threadIdx.x;
    const int warp = tid >> 5;
    const int lane = tid & 31;
    const int j0   = blockIdx.x * 8;
    const int o0   = blockIdx.x * 2;
    const int role = warp >> 3;         // 0: z1 warps 0-7, 1: z2 warps 8-15
    const int jl   = warp & 7;
    const int j    = j0 + jl;
    const unsigned grp = (unsigned)blockIdx.x / GSIZE;

    // ---- preload recurrent weights into registers ----
    float wreg[32];
    for (int round = 0; round < 2; round++) {
        const float* W = round ? W_rec2 : W_rec1;
        for (int idx = tid; idx < 1024 * 8; idx += BLOCK) {
            int k = idx >> 3, c = idx & 7;
            stage[k * 9 + c] = W[k * 1024 + j0 + c];
        }
        __syncthreads();
        if (role == round) {
            #pragma unroll
            for (int c = 0; c < 8; c++) {
                int k0 = c * 128 + lane * 4;
                wreg[4*c+0] = stage[(k0 + 0) * 9 + jl];
                wreg[4*c+1] = stage[(k0 + 1) * 9 + jl];
                wreg[4*c+2] = stage[(k0 + 2) * 9 + jl];
                wreg[4*c+3] = stage[(k0 + 3) * 9 + jl];
            }
        }
        __syncthreads();
    }

    // preload this CTA's two W_out columns + biases into SMEM
    for (int idx = tid; idx < 2048; idx += BLOCK) {
        int jj = idx >> 1, c = idx & 1;
        wout_s[c * 1024 + jj] = W_out[jj * 256 + o0 + c];
    }
    const int   ow   = warp - 8;                 // out-warp id 0..3 (warps 8-11)
    const float obia = (ow >= 0 && ow < 4) ? b_out[o0 + (ow & 1)] : 0.0f;
    __syncthreads();

    float z2reg = 0.0f;

    for (int i = 0; i < NSTEP; i++) {
        const int par = i & 1;
        const int pw  = par ^ 1;

        const float u = g_U[role][i][j];   // warp-uniform broadcast

        // Phase A: stage state into SMEM (+ z1 snapshot for out-GEMV)
        {
            float4 q = ldcg4(((const float4*)g_z[par]) + tid); // {z1a,z2a,z1b,z2b}
            ((float2*)e1)[tid]  = make_float2(q.x + q.y, q.z + q.w);
            ((float2*)e2)[tid]  = make_float2(q.y, q.w);
            ((float2*)(z1s + par * 1024))[tid] = make_float2(q.x, q.z);
        }
        __syncthreads();

        // Phase B: recurrent dots (and, on odd steps, out-GEMV in warps 8-11)
        if (role == 0 || (i & 1) == 0) {
            const float4* ev = (const float4*)(role ? e2 : e1);
            float a0 = 0.0f, a1 = 0.0f;
            #pragma unroll
            for (int c = 0; c < 8; c++) {
                float4 q = ev[c * 32 + lane];
                a0 += wreg[4*c+0] * q.x + wreg[4*c+1] * q.y;
                a1 += wreg[4*c+2] * q.z + wreg[4*c+3] * q.w;
            }
            float acc = a0 + a1;
            #pragma unroll
            for (int off = 16; off; off >>= 1)
                acc += __shfl_xor_sync(0xffffffffu, acc, off);
            if (role == 0) {
                if (lane == 0) ((float*)&g_z[pw][j])[0] = tanhf(acc + u);
            } else {
                z2reg = tanhf(acc + u);
                if (lane == 0) ((float*)&g_z[pw][j])[1] = z2reg;
            }
        } else {
            // odd step: idle z2-warps 8-11 compute out[i-2], out[i-1]
            if (ow >= 0 && ow < 4) {
                const int t_sel = ow >> 1;           // 0: out[i-2], 1: out[i-1]
                const int o_sel = ow & 1;
                if (!(t_sel == 0 && i == 1)) {
                    const float4* wv = (const float4*)(wout_s + o_sel * 1024);
                    const float4* zv = (const float4*)(z1s + t_sel * 1024);
                    float a0 = 0.0f, a1 = 0.0f;
                    #pragma unroll
                    for (int c = 0; c < 8; c++) {
                        float4 wq = wv[c * 32 + lane];
                        float4 zq = zv[c * 32 + lane];
                        a0 += wq.x * zq.x + wq.y * zq.y;
                        a1 += wq.z * zq.z + wq.w * zq.w;
                    }
                    float acc = a0 + a1;
                    #pragma unroll
                    for (int off = 16; off; off >>= 1)
                        acc += __shfl_xor_sync(0xffffffffu, acc, off);
                    if (lane == 0)
                        out[(size_t)(i - 2 + t_sel) * 256 + o0 + o_sel] =
                            tanhf(acc + obia);
                }
            }
        }
        // odd step: publish held z2 (owner z2-warp, lane 0)
        if (role == 1 && (i & 1) == 1 && lane == 0)
            ((float*)&g_z[pw][j])[1] = z2reg;
        __syncthreads();   // all publishes issued before arrive

        // hierarchical group-counter barrier
        if (i + 1 < NSTEP)
            gbar(tid, warp, lane, grp, (unsigned)(i + 1));
    }

    // Tail: final barrier round, then out[255] from z1(256)
    gbar(tid, warp, lane, grp, (unsigned)NSTEP);
    {
        float4 q = ldcg4(((const float4*)g_z[0]) + tid);   // z(256) lives in g_z[0]
        ((float2*)z1s)[tid] = make_float2(q.x, q.z);
        __syncthreads();
        if (ow == 0 || ow == 1) {          // warps 8, 9
            const float4* wv = (const float4*)(wout_s + ow * 1024);
            const float4* zv = (const float4*)z1s;
            float a0 = 0.0f, a1 = 0.0f;
            #pragma unroll
            for (int c = 0; c < 8; c++) {
                float4 wq = wv[c * 32 + lane];
                float4 zq = zv[c * 32 + lane];
                a0 += wq.x * zq.x + wq.y * zq.y;
                a1 += wq.z * zq.z + wq.w * zq.w;
            }
            float acc = a0 + a1;
            #pragma unroll
            for (int off = 16; off; off >>= 1)
                acc += __shfl_xor_sync(0xffffffffu, acc, off);
            if (lane == 0)
                out[(size_t)255 * 256 + o0 + ow] = tanhf(acc + b_out[o0 + ow]);
        }
    }
}

extern "C" void kernel_launch(void* const* d_in, const int* in_sizes, int n_in,
                              void* d_out, int out_size) {
    (void)in_sizes; (void)n_in; (void)out_size;
    const float* x      = (const float*)d_in[0];
    const float* W_in1  = (const float*)d_in[1];
    const float* b_in1  = (const float*)d_in[2];
    const float* W_rec1 = (const float*)d_in[3];
    const float* W_in2  = (const float*)d_in[4];
    const float* b_in2  = (const float*)d_in[5];
    const float* W_rec2 = (const float*)d_in[6];
    const float* W_out  = (const float*)d_in[7];
    const float* b_out  = (const float*)d_in[8];
    float* out = (float*)d_out;

    const size_t smem_bytes =
        (size_t)(1024 + 1024 + 2048 + 2048 + 1024 * 9) * sizeof(float); // 61.4 KB
    cudaFuncSetAttribute(rnn_main_kernel,
                         cudaFuncAttributeMaxDynamicSharedMemorySize,
                         (int)smem_bytes);

    rnn_init_kernel<<<1, 1024>>>();
    u_kernel<<<256, 256>>>(x, W_in1, b_in1, W_in2, b_in2);
    rnn_main_kernel<<<GRID, BLOCK, smem_bytes>>>(W_rec1, W_rec2, W_out, b_out, out);
}

// round 11
// speedup vs baseline: 1.0615x; 1.0615x over previous
#include <cuda_runtime.h>

// AlarmworkRNN collapsed to a vector RNN (only sequence row 2047 matters).
// Round 11: R9 scaffold, GRID 128->64 (2 outputs per warp, halved barrier
// participants/skew), init kernel folded into u_kernel block 0.

#define GRID  64
#define BLOCK 512
#define NSTEP 256

__device__ unsigned g_arrive;
__device__ float2 g_z[2][1024];           // parity-buffered {z1, z2}
__device__ float g_U[2][NSTEP][1024];     // u1/u2 per step (bias folded)

__device__ __forceinline__ void arrive_release(unsigned* p) {
    asm volatile("red.release.gpu.global.add.u32 [%0], %1;"
                 :: "l"(p), "r"(1u) : "memory");
}
__device__ __forceinline__ unsigned ld_acquire_gpu(unsigned* p) {
    unsigned v;
    asm volatile("ld.acquire.gpu.global.u32 %0, [%1];"
                 : "=r"(v) : "l"(p) : "memory");
    return v;
}
__device__ __forceinline__ float4 ldcg4(const float4* p) {
    float4 u;
    asm volatile("ld.global.cg.v4.f32 {%0,%1,%2,%3}, [%4];"
                 : "=f"(u.x), "=f"(u.y), "=f"(u.z), "=f"(u.w)
                 : "l"(p) : "memory");
    return u;
}

// ---- k1: U[m][t][j] = x[t,2047,:] @ W_in_m[:,j] + b_m[j]; block 0 also
//      resets the barrier counter and zero state (replaces init kernel) ----
__global__ __launch_bounds__(256)
void u_kernel(const float* __restrict__ x,
              const float* __restrict__ W_in1, const float* __restrict__ b_in1,
              const float* __restrict__ W_in2, const float* __restrict__ b_in2)
{
    __shared__ float xs[8][256];
    const int b   = blockIdx.x;
    const int tid = threadIdx.x;

    if (b == 0) {
        if (tid == 0) g_arrive = 0u;
        for (int idx = tid; idx < 1024; idx += 256)
            g_z[0][idx] = make_float2(0.0f, 0.0f);
    }

    const int m   = b >> 7;
    const int jt  = (b >> 5) & 3;
    const int t0  = (b & 31) * 8;
    const float* W  = m ? W_in2 : W_in1;
    const float* bi = m ? b_in2 : b_in1;

    for (int i = tid; i < 8 * 256; i += 256) {
        int tr = i >> 8, k = i & 255;
        xs[tr][k] = x[((size_t)(t0 + tr) * 2048 + 2047) * 256 + k];
    }
    __syncthreads();

    const int j = jt * 256 + tid;
    float acc[8];
    const float bj = bi[j];
    #pragma unroll
    for (int r = 0; r < 8; r++) acc[r] = bj;
    #pragma unroll 8
    for (int k = 0; k < 256; k++) {
        float w = W[k * 1024 + j];
        #pragma unroll
        for (int r = 0; r < 8; r++) acc[r] += xs[r][k] * w;
    }
    #pragma unroll
    for (int r = 0; r < 8; r++) g_U[m][t0 + r][j] = acc[r];
}

// ---- k2: persistent recurrence + in-loop out ----
__global__ __launch_bounds__(BLOCK, 1)
void rnn_main_kernel(const float* __restrict__ W_rec1,
                     const float* __restrict__ W_rec2,
                     const float* __restrict__ W_out,
                     const float* __restrict__ b_out,
                     float* __restrict__ out)
{
    extern __shared__ float sm[];
    float* e1     = sm;                 // [1024]  z1 + z2
    float* e2     = e1 + 1024;          // [1024]  z2
    float* z1s    = e2 + 1024;          // [2][1024] z1 snapshots by parity
    float* wout_s = z1s + 2048;         // [4][1024] this CTA's W_out columns
    float* stage  = wout_s + 4096;      // [1024*17] weight staging (preload only)

    const int tid  = threadIdx.x;
    const int warp = tid >> 5;
    const int lane = tid & 31;
    const int j0   = blockIdx.x * 16;   // 16 outputs per CTA
    const int o0   = blockIdx.x * 4;    // 4 final-out columns per CTA
    const int role = warp >> 3;         // 0: z1 warps 0-7, 1: z2 warps 8-15
    const int p8   = warp & 7;
    const int j_a  = j0 + 2 * p8;       // this warp's output pair
    const int j_b  = j_a + 1;

    // ---- preload recurrent weights: 2 outputs per warp ----
    float wregA[32], wregB[32];
    for (int round = 0; round < 2; round++) {
        const float* W = round ? W_rec2 : W_rec1;
        for (int idx = tid; idx < 1024 * 16; idx += BLOCK) {
            int k = idx >> 4, c = idx & 15;
            stage[k * 17 + c] = W[k * 1024 + j0 + c];
        }
        __syncthreads();
        if (role == round) {
            #pragma unroll
            for (int c = 0; c < 8; c++) {
                int k0 = c * 128 + lane * 4;
                #pragma unroll
                for (int s = 0; s < 4; s++) {
                    wregA[4*c+s] = stage[(k0 + s) * 17 + 2 * p8];
                    wregB[4*c+s] = stage[(k0 + s) * 17 + 2 * p8 + 1];
                }
            }
        }
        __syncthreads();
    }

    // preload this CTA's four W_out columns into SMEM
    for (int idx = tid; idx < 4096; idx += BLOCK) {
        int jj = idx >> 2, c = idx & 3;
        wout_s[c * 1024 + jj] = W_out[jj * 256 + o0 + c];
    }
    const int   ow   = warp - 8;                 // 0..7 active out-warps (8-15)
    const float obia = (ow >= 0) ? b_out[o0 + (ow & 3)] : 0.0f;
    __syncthreads();

    float z2regA = 0.0f, z2regB = 0.0f;

    for (int i = 0; i < NSTEP; i++) {
        const int par = i & 1;
        const int pw  = par ^ 1;

        const float uA = g_U[role][i][j_a];   // warp-uniform broadcasts
        const float uB = g_U[role][i][j_b];

        // Phase A: stage state into SMEM (+ z1 snapshot for out-GEMV)
        {
            float4 q = ldcg4(((const float4*)g_z[par]) + tid); // {z1a,z2a,z1b,z2b}
            ((float2*)e1)[tid]  = make_float2(q.x + q.y, q.z + q.w);
            ((float2*)e2)[tid]  = make_float2(q.y, q.w);
            ((float2*)(z1s + par * 1024))[tid] = make_float2(q.x, q.z);
        }
        __syncthreads();

        // Phase B: recurrent dots (2 outputs per warp, shared LDS stream)
        if (role == 0 || (i & 1) == 0) {
            const float4* ev = (const float4*)(role ? e2 : e1);
            float aA = 0.0f, aB = 0.0f;
            #pragma unroll
            for (int c = 0; c < 8; c++) {
                float4 q = ev[c * 32 + lane];
                aA += wregA[4*c+0] * q.x + wregA[4*c+1] * q.y
                    + wregA[4*c+2] * q.z + wregA[4*c+3] * q.w;
                aB += wregB[4*c+0] * q.x + wregB[4*c+1] * q.y
                    + wregB[4*c+2] * q.z + wregB[4*c+3] * q.w;
            }
            #pragma unroll
            for (int off = 16; off; off >>= 1) {
                aA += __shfl_xor_sync(0xffffffffu, aA, off);
                aB += __shfl_xor_sync(0xffffffffu, aB, off);
            }
            if (role == 0) {
                if (lane == 0) {
                    ((float*)&g_z[pw][j_a])[0] = tanhf(aA + uA);
                    ((float*)&g_z[pw][j_b])[0] = tanhf(aB + uB);
                }
            } else {
                z2regA = tanhf(aA + uA);
                z2regB = tanhf(aB + uB);
                if (lane == 0) {
                    ((float*)&g_z[pw][j_a])[1] = z2regA;
                    ((float*)&g_z[pw][j_b])[1] = z2regB;
                }
            }
        } else {
            // odd step: idle z2-warps 8-15 compute out[i-2], out[i-1] (4 cols)
            if (ow >= 0) {
                const int t_sel = ow >> 2;           // 0: out[i-2], 1: out[i-1]
                const int o_sel = ow & 3;
                if (!(t_sel == 0 && i == 1)) {
                    const float4* wv = (const float4*)(wout_s + o_sel * 1024);
                    const float4* zv = (const float4*)(z1s + t_sel * 1024);
                    float a0 = 0.0f, a1 = 0.0f;
                    #pragma unroll
                    for (int c = 0; c < 8; c++) {
                        float4 wq = wv[c * 32 + lane];
                        float4 zq = zv[c * 32 + lane];
                        a0 += wq.x * zq.x + wq.y * zq.y;
                        a1 += wq.z * zq.z + wq.w * zq.w;
                    }
                    float acc = a0 + a1;
                    #pragma unroll
                    for (int off = 16; off; off >>= 1)
                        acc += __shfl_xor_sync(0xffffffffu, acc, off);
                    if (lane == 0)
                        out[(size_t)(i - 2 + t_sel) * 256 + o0 + o_sel] =
                            tanhf(acc + obia);
                }
            }
        }
        // odd step: publish held z2 (owner z2-warp, lane 0)
        if (role == 1 && (i & 1) == 1 && lane == 0) {
            ((float*)&g_z[pw][j_a])[1] = z2regA;
            ((float*)&g_z[pw][j_b])[1] = z2regB;
        }
        __syncthreads();   // all publishes issued before arrive

        // single-counter barrier (R7-proven)
        if (i + 1 < NSTEP) {
            if (tid == 0) {
                arrive_release(&g_arrive);
                const unsigned target = (unsigned)(i + 1) * GRID;
                while (ld_acquire_gpu(&g_arrive) < target) { }
            }
            __syncthreads();
        }
    }

    // Tail: final barrier round, then out[255] from z1(256)
    if (tid == 0) {
        arrive_release(&g_arrive);
        const unsigned target = (unsigned)NSTEP * GRID;
        while (ld_acquire_gpu(&g_arrive) < target) { }
    }
    __syncthreads();
    {
        float4 q = ldcg4(((const float4*)g_z[0]) + tid);   // z(256) in g_z[0]
        ((float2*)z1s)[tid] = make_float2(q.x, q.z);
        __syncthreads();
        if (ow >= 0 && ow < 4) {           // warps 8-11: cols o0+0..3
            const float4* wv = (const float4*)(wout_s + ow * 1024);
            const float4* zv = (const float4*)z1s;
            float a0 = 0.0f, a1 = 0.0f;
            #pragma unroll
            for (int c = 0; c < 8; c++) {
                float4 wq = wv[c * 32 + lane];
                float4 zq = zv[c * 32 + lane];
                a0 += wq.x * zq.x + wq.y * zq.y;
                a1 += wq.z * zq.z + wq.w * zq.w;
            }
            float acc = a0 + a1;
            #pragma unroll
            for (int off = 16; off; off >>= 1)
                acc += __shfl_xor_sync(0xffffffffu, acc, off);
            if (lane == 0)
                out[(size_t)255 * 256 + o0 + ow] = tanhf(acc + b_out[o0 + ow]);
        }
    }
}

extern "C" void kernel_launch(void* const* d_in, const int* in_sizes, int n_in,
                              void* d_out, int out_size) {
    (void)in_sizes; (void)n_in; (void)out_size;
    const float* x      = (const float*)d_in[0];
    const float* W_in1  = (const float*)d_in[1];
    const float* b_in1  = (const float*)d_in[2];
    const float* W_rec1 = (const float*)d_in[3];
    const float* W_in2  = (const float*)d_in[4];
    const float* b_in2  = (const float*)d_in[5];
    const float* W_rec2 = (const float*)d_in[6];
    const float* W_out  = (const float*)d_in[7];
    const float* b_out  = (const float*)d_in[8];
    float* out = (float*)d_out;

    const size_t smem_bytes =
        (size_t)(1024 + 1024 + 2048 + 4096 + 1024 * 17) * sizeof(float); // 102.4 KB
    cudaFuncSetAttribute(rnn_main_kernel,
                         cudaFuncAttributeMaxDynamicSharedMemorySize,
                         (int)smem_bytes);

    u_kernel<<<256, 256>>>(x, W_in1, b_in1, W_in2, b_in2);
    rnn_main_kernel<<<GRID, BLOCK, smem_bytes>>>(W_rec1, W_rec2, W_out, b_out, out);
}

// round 12
// speedup vs baseline: 1.0788x; 1.0163x over previous
#include <cuda_runtime.h>

// AlarmworkRNN collapsed to a vector RNN (only sequence row 2047 matters).
// Round 12: R9 scaffold (best: 538.8us) with
//   - odd-step split barrier: out-GEMV moved into the global-barrier wait
//     window (bar.arrive by warps 8-15, bar.sync by warps 0-7), so the
//     arrive is no longer gated by out work;
//   - init kernel folded into u_kernel block 0.

#define GRID  128
#define BLOCK 512
#define NSTEP 256

__device__ unsigned g_arrive;
__device__ float2 g_z[2][1024];           // parity-buffered {z1, z2}
__device__ float g_U[2][NSTEP][1024];     // u1/u2 per step (bias folded)

__device__ __forceinline__ void arrive_release(unsigned* p) {
    asm volatile("red.release.gpu.global.add.u32 [%0], %1;"
                 :: "l"(p), "r"(1u) : "memory");
}
__device__ __forceinline__ unsigned ld_acquire_gpu(unsigned* p) {
    unsigned v;
    asm volatile("ld.acquire.gpu.global.u32 %0, [%1];"
                 : "=r"(v) : "l"(p) : "memory");
    return v;
}
__device__ __forceinline__ float4 ldcg4(const float4* p) {
    float4 u;
    asm volatile("ld.global.cg.v4.f32 {%0,%1,%2,%3}, [%4];"
                 : "=f"(u.x), "=f"(u.y), "=f"(u.z), "=f"(u.w)
                 : "l"(p) : "memory");
    return u;
}
#define BAR_SYNC(id, n)   asm volatile("bar.sync %0, %1;"   :: "r"(id), "r"(n) : "memory")
#define BAR_ARRIVE(id, n) asm volatile("bar.arrive %0, %1;" :: "r"(id), "r"(n) : "memory")

// ---- k1: U[m][t][j] = x[t,2047,:] @ W_in_m[:,j] + b_m[j]; block 0 also
//      resets the barrier counter and zeroes state (init kernel folded) ----
__global__ __launch_bounds__(256)
void u_kernel(const float* __restrict__ x,
              const float* __restrict__ W_in1, const float* __restrict__ b_in1,
              const float* __restrict__ W_in2, const float* __restrict__ b_in2)
{
    __shared__ float xs[8][256];
    const int b   = blockIdx.x;
    const int tid = threadIdx.x;

    if (b == 0) {
        if (tid == 0) g_arrive = 0u;
        for (int idx = tid; idx < 1024; idx += 256)
            g_z[0][idx] = make_float2(0.0f, 0.0f);
    }

    const int m   = b >> 7;
    const int jt  = (b >> 5) & 3;
    const int t0  = (b & 31) * 8;
    const float* W  = m ? W_in2 : W_in1;
    const float* bi = m ? b_in2 : b_in1;

    for (int i = tid; i < 8 * 256; i += 256) {
        int tr = i >> 8, k = i & 255;
        xs[tr][k] = x[((size_t)(t0 + tr) * 2048 + 2047) * 256 + k];
    }
    __syncthreads();

    const int j = jt * 256 + tid;
    float acc[8];
    const float bj = bi[j];
    #pragma unroll
    for (int r = 0; r < 8; r++) acc[r] = bj;
    #pragma unroll 8
    for (int k = 0; k < 256; k++) {
        float w = W[k * 1024 + j];
        #pragma unroll
        for (int r = 0; r < 8; r++) acc[r] += xs[r][k] * w;
    }
    #pragma unroll
    for (int r = 0; r < 8; r++) g_U[m][t0 + r][j] = acc[r];
}

// ---- k2: persistent recurrence + in-loop out ----
__global__ __launch_bounds__(BLOCK, 1)
void rnn_main_kernel(const float* __restrict__ W_rec1,
                     const float* __restrict__ W_rec2,
                     const float* __restrict__ W_out,
                     const float* __restrict__ b_out,
                     float* __restrict__ out)
{
    extern __shared__ float sm[];
    float* e1     = sm;                 // [1024]  z1 + z2
    float* e2     = e1 + 1024;          // [1024]  z2
    float* z1s    = e2 + 1024;          // [2][1024] z1 snapshots by parity
    float* wout_s = z1s + 2048;         // [2][1024] this CTA's W_out columns
    float* stage  = wout_s + 2048;      // [1024*9] weight staging (preload only)

    const int tid  = threadIdx.x;
    const int warp = tid >> 5;
    const int lane = tid & 31;
    const int j0   = blockIdx.x * 8;
    const int o0   = blockIdx.x * 2;
    const int role = warp >> 3;         // 0: z1 warps 0-7, 1: z2 warps 8-15
    const int jl   = warp & 7;
    const int j    = j0 + jl;

    // ---- preload recurrent weights into registers ----
    float wreg[32];
    for (int round = 0; round < 2; round++) {
        const float* W = round ? W_rec2 : W_rec1;
        for (int idx = tid; idx < 1024 * 8; idx += BLOCK) {
            int k = idx >> 3, c = idx & 7;
            stage[k * 9 + c] = W[k * 1024 + j0 + c];
        }
        __syncthreads();
        if (role == round) {
            #pragma unroll
            for (int c = 0; c < 8; c++) {
                int k0 = c * 128 + lane * 4;
                wreg[4*c+0] = stage[(k0 + 0) * 9 + jl];
                wreg[4*c+1] = stage[(k0 + 1) * 9 + jl];
                wreg[4*c+2] = stage[(k0 + 2) * 9 + jl];
                wreg[4*c+3] = stage[(k0 + 3) * 9 + jl];
            }
        }
        __syncthreads();
    }

    // preload this CTA's two W_out columns + biases into SMEM
    for (int idx = tid; idx < 2048; idx += BLOCK) {
        int jj = idx >> 1, c = idx & 1;
        wout_s[c * 1024 + jj] = W_out[jj * 256 + o0 + c];
    }
    const int   ow   = warp - 8;                 // out-warp id 0..3 (warps 8-11)
    const float obia = (ow >= 0 && ow < 4) ? b_out[o0 + (ow & 1)] : 0.0f;
    __syncthreads();

    float z2reg = 0.0f;

    for (int i = 0; i < NSTEP; i++) {
        const int par = i & 1;
        const int pw  = par ^ 1;

        const float u = g_U[role][i][j];   // warp-uniform broadcast

        // Phase A: stage state into SMEM (+ z1 snapshot for out-GEMV)
        {
            float4 q = ldcg4(((const float4*)g_z[par]) + tid); // {z1a,z2a,z1b,z2b}
            ((float2*)e1)[tid]  = make_float2(q.x + q.y, q.z + q.w);
            ((float2*)e2)[tid]  = make_float2(q.y, q.w);
            ((float2*)(z1s + par * 1024))[tid] = make_float2(q.x, q.z);
        }
        __syncthreads();

        if ((i & 1) == 0) {
            // ---- EVEN step: both recurrent dots, standard barrier ----
            const float4* ev = (const float4*)(role ? e2 : e1);
            float a0 = 0.0f, a1 = 0.0f;
            #pragma unroll
            for (int c = 0; c < 8; c++) {
                float4 q = ev[c * 32 + lane];
                a0 += wreg[4*c+0] * q.x + wreg[4*c+1] * q.y;
                a1 += wreg[4*c+2] * q.z + wreg[4*c+3] * q.w;
            }
            float acc = a0 + a1;
            #pragma unroll
            for (int off = 16; off; off >>= 1)
                acc += __shfl_xor_sync(0xffffffffu, acc, off);
            if (role == 0) {
                if (lane == 0) ((float*)&g_z[pw][j])[0] = tanhf(acc + u);
            } else {
                z2reg = tanhf(acc + u);
                if (lane == 0) ((float*)&g_z[pw][j])[1] = z2reg;
            }
            __syncthreads();   // all publishes issued before arrive
            if (i + 1 < NSTEP) {
                if (tid == 0) {
                    arrive_release(&g_arrive);
                    const unsigned target = (unsigned)(i + 1) * GRID;
                    while (ld_acquire_gpu(&g_arrive) < target) { }
                }
            }
            __syncthreads();
        } else {
            // ---- ODD step: z2 holds; split barrier; out-GEMV in wait window ----
            if (warp < 8) {
                // z1 GEMV + publish, then gate the arrive
                const float4* ev = (const float4*)e1;
                float a0 = 0.0f, a1 = 0.0f;
                #pragma unroll
                for (int c = 0; c < 8; c++) {
                    float4 q = ev[c * 32 + lane];
                    a0 += wreg[4*c+0] * q.x + wreg[4*c+1] * q.y;
                    a1 += wreg[4*c+2] * q.z + wreg[4*c+3] * q.w;
                }
                float acc = a0 + a1;
                #pragma unroll
                for (int off = 16; off; off >>= 1)
                    acc += __shfl_xor_sync(0xffffffffu, acc, off);
                if (lane == 0) ((float*)&g_z[pw][j])[0] = tanhf(acc + u);
                BAR_SYNC(1, BLOCK);
                if (i + 1 < NSTEP && tid == 0) {
                    arrive_release(&g_arrive);
                    const unsigned target = (unsigned)(i + 1) * GRID;
                    while (ld_acquire_gpu(&g_arrive) < target) { }
                }
            } else {
                // z2 hold publish (register, instant), arrive without blocking,
                // then out-GEMV concurrent with the global barrier
                if (lane == 0) ((float*)&g_z[pw][j])[1] = z2reg;
                BAR_ARRIVE(1, BLOCK);
                if (ow < 4) {
                    const int t_sel = ow >> 1;       // 0: out[i-2], 1: out[i-1]
                    const int o_sel = ow & 1;
                    if (!(t_sel == 0 && i == 1)) {
                        const float4* wv = (const float4*)(wout_s + o_sel * 1024);
                        const float4* zv = (const float4*)(z1s + t_sel * 1024);
                        float a0 = 0.0f, a1 = 0.0f;
                        #pragma unroll
                        for (int c = 0; c < 8; c++) {
                            float4 wq = wv[c * 32 + lane];
                            float4 zq = zv[c * 32 + lane];
                            a0 += wq.x * zq.x + wq.y * zq.y;
                            a1 += wq.z * zq.z + wq.w * zq.w;
                        }
                        float acc = a0 + a1;
                        #pragma unroll
                        for (int off = 16; off; off >>= 1)
                            acc += __shfl_xor_sync(0xffffffffu, acc, off);
                        if (lane == 0)
                            out[(size_t)(i - 2 + t_sel) * 256 + o0 + o_sel] =
                                tanhf(acc + obia);
                    }
                }
            }
            __syncthreads();   // everyone meets before next Phase A
        }
    }

    // Tail: final barrier round, then out[255] from z1(256)
    if (tid == 0) {
        arrive_release(&g_arrive);
        const unsigned target = (unsigned)NSTEP * GRID;
        while (ld_acquire_gpu(&g_arrive) < target) { }
    }
    __syncthreads();
    {
        float4 q = ldcg4(((const float4*)g_z[0]) + tid);   // z(256) lives in g_z[0]
        ((float2*)z1s)[tid] = make_float2(q.x, q.z);
        __syncthreads();
        if (ow == 0 || ow == 1) {          // warps 8, 9
            const float4* wv = (const float4*)(wout_s + ow * 1024);
            const float4* zv = (const float4*)z1s;
            float a0 = 0.0f, a1 = 0.0f;
            #pragma unroll
            for (int c = 0; c < 8; c++) {
                float4 wq = wv[c * 32 + lane];
                float4 zq = zv[c * 32 + lane];
                a0 += wq.x * zq.x + wq.y * zq.y;
                a1 += wq.z * zq.z + wq.w * zq.w;
            }
            float acc = a0 + a1;
            #pragma unroll
            for (int off = 16; off; off >>= 1)
                acc += __shfl_xor_sync(0xffffffffu, acc, off);
            if (lane == 0)
                out[(size_t)255 * 256 + o0 + ow] = tanhf(acc + b_out[o0 + ow]);
        }
    }
}

extern "C" void kernel_launch(void* const* d_in, const int* in_sizes, int n_in,
                              void* d_out, int out_size) {
    (void)in_sizes; (void)n_in; (void)out_size;
    const float* x      = (const float*)d_in[0];
    const float* W_in1  = (const float*)d_in[1];
    const float* b_in1  = (const float*)d_in[2];
    const float* W_rec1 = (const float*)d_in[3];
    const float* W_in2  = (const float*)d_in[4];
    const float* b_in2  = (const float*)d_in[5];
    const float* W_rec2 = (const float*)d_in[6];
    const float* W_out  = (const float*)d_in[7];
    const float* b_out  = (const float*)d_in[8];
    float* out = (float*)d_out;

    const size_t smem_bytes =
        (size_t)(1024 + 1024 + 2048 + 2048 + 1024 * 9) * sizeof(float); // 61.4 KB
    cudaFuncSetAttribute(rnn_main_kernel,
                         cudaFuncAttributeMaxDynamicSharedMemorySize,
                         (int)smem_bytes);

    u_kernel<<<256, 256>>>(x, W_in1, b_in1, W_in2, b_in2);
    rnn_main_kernel<<<GRID, BLOCK, smem_bytes>>>(W_rec1, W_rec2, W_out, b_out, out);
}